// round 4
// baseline (speedup 1.0000x reference)
#include <cuda_runtime.h>
#include <cstdint>

// ---------------------------------------------------------------------------
// LSTM Neural Hawkes Process NLL  (B=64, L=1024, H=64)
// R4: two interleaved batches per CTA (shared weight registers, independent
//     dependency chains fill each other's latency), deferred gate-6 math,
//     post-barrier state stores.
// ---------------------------------------------------------------------------

#define BATCH   64
#define MAXL    1024
#define LP1     1025
#define HID     64
#define SEVENH  448
#define NMC     30
#define T_END   100.0f
#define EPS_L   1e-10f
#define TOTAL   (BATCH * LP1)          // 65600
#define LOG2E   1.4426950408889634f
#define LN2     0.6931471805599453f

// ------------------------- device scratch (no mallocs) ---------------------
__device__ float4 g_state [TOTAL * HID];   // {c, cbar, o, dec}
__device__ float  g_before[TOTAL * HID];
__device__ float  g_dt    [TOTAL];
__device__ float  g_part  [TOTAL];

// ------------------------------ fast math -----------------------------------
__device__ __forceinline__ float ex2f(float x){ float y; asm("ex2.approx.f32 %0,%1;":"=f"(y):"f"(x)); return y; }
__device__ __forceinline__ float lg2f(float x){ float y; asm("lg2.approx.f32 %0,%1;":"=f"(y):"f"(x)); return y; }
__device__ __forceinline__ float tanh_mufu(float x){ float y; asm("tanh.approx.f32 %0,%1;":"=f"(y):"f"(x)); return y; }
__device__ __forceinline__ float fsig(float x){ return fmaf(0.5f, tanh_mufu(0.5f * x), 0.5f); }
__device__ __forceinline__ float fsoftplus(float x){
    return fmaxf(x, 0.0f) + LN2 * lg2f(1.0f + ex2f(-fabsf(x) * LOG2E));
}
__device__ __forceinline__ float flog(float x){ return LN2 * lg2f(x); }

// ------------------------------ packed f32x2 --------------------------------
__device__ __forceinline__ void fma2(unsigned long long& d, unsigned long long a, unsigned long long b){
    asm("fma.rn.f32x2 %0, %1, %2, %0;" : "+l"(d) : "l"(a), "l"(b));
}
__device__ __forceinline__ void add2(unsigned long long& d, unsigned long long a){
    asm("add.rn.f32x2 %0, %1, %0;" : "+l"(d) : "l"(a));
}
__device__ __forceinline__ unsigned long long pack2(float lo, float hi){
    unsigned long long r; asm("mov.b64 %0, {%1,%2};" : "=l"(r) : "f"(lo), "f"(hi)); return r;
}
__device__ __forceinline__ float2 unpack2(unsigned long long v){
    float2 r; asm("mov.b64 {%0,%1}, %2;" : "=f"(r.x), "=f"(r.y) : "l"(v)); return r;
}

// ------------------------------ named barriers ------------------------------
#define BAR_SYNC(id, cnt)   asm volatile("bar.sync %0, %1;"   :: "r"(id), "r"(cnt) : "memory")
#define BAR_ARRIVE(id, cnt) asm volatile("bar.arrive %0, %1;" :: "r"(id), "r"(cnt) : "memory")

// ------------------------------ Threefry-2x32-20 ----------------------------
__device__ __forceinline__ uint32_t rotl32(uint32_t x, int r){ return (x << r) | (x >> (32 - r)); }
__device__ __forceinline__ float tf_uniform(uint32_t flat){
    // JAX partitionable threefry, key (0,42): bits = out0 ^ out1
    uint32_t k0 = 0u, k1 = 42u, ks2 = k0 ^ k1 ^ 0x1BD11BDAu;
    uint32_t x0 = 0u + k0, x1 = flat + k1;
#define TF_R(r) { x0 += x1; x1 = rotl32(x1, (r)); x1 ^= x0; }
    TF_R(13) TF_R(15) TF_R(26) TF_R(6)   x0 += k1;  x1 += ks2 + 1u;
    TF_R(17) TF_R(29) TF_R(16) TF_R(24)  x0 += ks2; x1 += k0  + 2u;
    TF_R(13) TF_R(15) TF_R(26) TF_R(6)   x0 += k0;  x1 += k1  + 3u;
    TF_R(17) TF_R(29) TF_R(16) TF_R(24)  x0 += k1;  x1 += ks2 + 4u;
    TF_R(13) TF_R(15) TF_R(26) TF_R(6)   x0 += ks2; x1 += k0  + 5u;
#undef TF_R
    uint32_t bits = x0 ^ x1;
    return __uint_as_float((bits >> 9) | 0x3F800000u) - 1.0f;
}

// ------------------------------ Kernel 1: scan -------------------------------
// One CTA per TWO batches, 448 threads (one per GEMM column, weights loaded
// once and reused for both batches). Two independent recurrences interleave:
// each fills the other's barrier/epilogue/MUFU latency. Epilogue on warps
// 12/13 (thread 384+ch is the gate-6 thread for channel ch in BOTH batches).
__global__ void __launch_bounds__(SEVENH, 1)
scan_kernel(const float* __restrict__ seq,    // [B, L, 1]
            const float* __restrict__ Wrec,   // [65, 448]
            const float* __restrict__ brec,   // [448]
            const int*   __restrict__ lens)   // [B]
{
    __shared__ __align__(16) float s_h[2][HID];
    __shared__ float s_v[2][SEVENH];
    __shared__ float s_dt[2][LP1];

    const int bA = blockIdx.x * 2;
    const int bB = bA + 1;
    const int j  = threadIdx.x;
    const int lenA = lens[bA];
    const int lenB = lens[bB];
    const int lmax = max(lenA, lenB);
    const float* spA = seq + bA * MAXL;
    const float* spB = seq + bB * MAXL;

    for (int l = j; l <= MAXL; l += SEVENH) {
        float vA, vB;
        if (l < lenA)        vA = (l == 0) ? spA[0] : spA[l] - spA[l - 1];
        else if (l == lenA)  vA = T_END - spA[lenA - 1];
        else                 vA = -1.0f;
        if (l < lenB)        vB = (l == 0) ? spB[0] : spB[l] - spB[l - 1];
        else if (l == lenB)  vB = T_END - spB[lenB - 1];
        else                 vB = -1.0f;
        s_dt[0][l] = vA;  g_dt[bA * LP1 + l] = vA;
        s_dt[1][l] = vB;  g_dt[bB * LP1 + l] = vB;
    }

    if (j >= 384) {                     // epilogue threads init state index 0
        const int ch = j - 384;
        s_h[0][ch] = 0.0f; s_h[1][ch] = 0.0f;
        g_state [(bA * LP1) * HID + ch] = make_float4(0.f, 0.f, 0.f, 0.f);
        g_state [(bB * LP1) * HID + ch] = make_float4(0.f, 0.f, 0.f, 0.f);
        g_before[(bA * LP1) * HID + ch] = 0.0f;
        g_before[(bB * LP1) * HID + ch] = 0.0f;
    }

    // column weights (shared across both batches): row 0 scalar + 32 f32x2
    const float w0 = Wrec[j];
    const float bj = brec[j];
    unsigned long long w2[32];
#pragma unroll
    for (int k = 0; k < 32; k++)
        w2[k] = pack2(Wrec[(2*k + 1) * SEVENH + j], Wrec[(2*k + 2) * SEVENH + j]);

    const int gate = j >> 6;            // 0:i 1:f 2:z 3:o 4:ib 5:fb 6:d
    float ctA = 0.0f, cbA = 0.0f;       // carries (epilogue threads only)
    float ctB = 0.0f, cbB = 0.0f;
    // deferred-store registers (epilogue threads)
    float stA_c=0, stA_cb=0, stA_o=0, stA_d=0, stA_bef=0;
    float stB_c=0, stB_cb=0, stB_o=0, stB_d=0, stB_bef=0;
    __syncthreads();

    for (int l = 0; l < lmax; l++) {
        const bool aA = l < lenA;
        const bool aB = l < lenB;
        const float dtA = s_dt[0][l];
        const float dtB = s_dt[1][l];

        // ---- phase 1: two packed-f32x2 dots against s_h[A], s_h[B]
        unsigned long long a0 = 0ull, a1 = 0ull, c0 = 0ull, c1 = 0ull;
        const ulonglong2* hA = reinterpret_cast<const ulonglong2*>(s_h[0]);
        const ulonglong2* hB = reinterpret_cast<const ulonglong2*>(s_h[1]);
#pragma unroll
        for (int q = 0; q < 8; q++) {
            ulonglong2 uA = hA[q], uB = hB[q];
            fma2(a0, w2[2*q],      uA.x);
            fma2(a1, w2[2*q + 1],  uA.y);
            fma2(c0, w2[2*q],      uB.x);
            fma2(c1, w2[2*q + 1],  uB.y);
            ulonglong2 vA = hA[q + 8], vB = hB[q + 8];
            fma2(a0, w2[2*q + 16], vA.x);
            fma2(a1, w2[2*q + 17], vA.y);
            fma2(c0, w2[2*q + 16], vB.x);
            fma2(c1, w2[2*q + 17], vB.y);
        }
        add2(a0, a1); add2(c0, c1);
        float2 rA = unpack2(a0), rB = unpack2(c0);
        const float accA = (rA.x + rA.y) + fmaf(w0, dtA, bj);
        const float accB = (rB.x + rB.y) + fmaf(w0, dtB, bj);

        if (j < 384) {
            // gates 0..5: nonlinearize and publish
            float nvA, nvB;
            if (gate == 2) { nvA = tanh_mufu(accA); nvB = tanh_mufu(accB); }
            else           { nvA = fsig(accA);      nvB = fsig(accB); }
            if (aA) s_v[0][j] = nvA;
            if (aB) s_v[1][j] = nvB;
            BAR_ARRIVE(1, SEVENH);     // release gates, don't wait
        } else {
            // gate 6 threads = epilogue threads; softplus/ex2 deferred past bar
            BAR_SYNC(1, SEVENH);
            const int ch = j - 384;
            if (aA) {
                const float dec = fsoftplus(accA);
                const float e   = ex2f(-dec * s_dt[0][l + 1] * LOG2E);
                const float iG = s_v[0][ch],        fG = s_v[0][ 64 + ch];
                const float zG = s_v[0][128 + ch],  oG = s_v[0][192 + ch];
                const float ib = s_v[0][256 + ch],  fb = s_v[0][320 + ch];
                const float c   = fmaf(fG, ctA, iG * zG);
                const float cb  = fmaf(fb, cbA, ib * zG);
                const float cd  = fmaf(c - cb, e, cb);
                const float bef = oG * tanh_mufu(cd);
                ctA = cd; cbA = cb;
                s_h[0][ch] = bef;
                stA_c = c; stA_cb = cb; stA_o = oG; stA_d = dec; stA_bef = bef;
            }
            if (aB) {
                const float dec = fsoftplus(accB);
                const float e   = ex2f(-dec * s_dt[1][l + 1] * LOG2E);
                const float iG = s_v[1][ch],        fG = s_v[1][ 64 + ch];
                const float zG = s_v[1][128 + ch],  oG = s_v[1][192 + ch];
                const float ib = s_v[1][256 + ch],  fb = s_v[1][320 + ch];
                const float c   = fmaf(fG, ctB, iG * zG);
                const float cb  = fmaf(fb, cbB, ib * zG);
                const float cd  = fmaf(c - cb, e, cb);
                const float bef = oG * tanh_mufu(cd);
                ctB = cd; cbB = cb;
                s_h[1][ch] = bef;
                stB_c = c; stB_cb = cb; stB_o = oG; stB_d = dec; stB_bef = bef;
            }
        }
        BAR_SYNC(2, SEVENH);           // h ready for everyone

        // deferred state stores (off the critical path; next GEMM already runs)
        if (j >= 384) {
            const int ch = j - 384;
            if (aA) {
                const int base = (bA * LP1 + l + 1) * HID + ch;
                g_state [base] = make_float4(stA_c, stA_cb, stA_o, stA_d);
                g_before[base] = stA_bef;
            }
            if (aB) {
                const int base = (bB * LP1 + l + 1) * HID + ch;
                g_state [base] = make_float4(stB_c, stB_cb, stB_o, stB_d);
                g_before[base] = stB_bef;
            }
        }
    }
}

// --------------------- Kernel 2: MC integral + log-intensity -----------------
// Warp per (b,l); lane = MC sample (30 active). Per-channel params pre-
// transformed into shared {m, A, cbar, o*wf}; inner loop is LDS-broadcast +
// 2 MUFU + 3 FMA per channel with zero shuffles.
__global__ void __launch_bounds__(256, 8)
mc_kernel(const float* __restrict__ Wf,    // [64]
          const float* __restrict__ bf,    // [1]
          const int*   __restrict__ lens)  // [B]
{
    __shared__ __align__(16) float4 s_st[8][HID];

    const int warp = threadIdx.x >> 5;
    const int wid  = blockIdx.x * 8 + warp;
    if (wid >= TOTAL) return;
    const int lane = threadIdx.x & 31;
    const int b = wid / LP1;
    const int l = wid - b * LP1;
    const int len = lens[b];

    float out = 0.0f;
    if (l <= len) {
        const float dtl = g_dt[wid];
        const float bfv = bf[0];
        const int base = wid * HID;
        const float wf0 = Wf[lane], wf1 = Wf[lane + 32];

        // stage transformed per-channel params + event-term partial dot
        const float4 s0 = g_state[base + lane];
        const float4 s1 = g_state[base + lane + 32];
        const float mscale = -dtl * LOG2E;
        s_st[warp][lane]      = make_float4(s0.w * mscale, s0.x - s0.y, s0.y, s0.z * wf0);
        s_st[warp][lane + 32] = make_float4(s1.w * mscale, s1.x - s1.y, s1.y, s1.z * wf1);

        float q = 0.0f;
        if (l < len)
            q = fmaf(g_before[base + lane], wf0, g_before[base + lane + 32] * wf1);
        __syncwarp();

        // lane s: full 64-channel intensity at random time u_s * dt
        float sp = 0.0f;
        if (lane < NMC) {
            const float u = tf_uniform((uint32_t)lane * (uint32_t)TOTAL + (uint32_t)wid);
            float acc0 = 0.0f, acc1 = 0.0f;
            const float4* st = s_st[warp];
#pragma unroll 8
            for (int ch = 0; ch < HID; ch += 2) {
                const float4 t0 = st[ch], t1 = st[ch + 1];
                acc0 = fmaf(t0.w, tanh_mufu(fmaf(t0.y, ex2f(u * t0.x), t0.z)), acc0);
                acc1 = fmaf(t1.w, tanh_mufu(fmaf(t1.y, ex2f(u * t1.x), t1.z)), acc1);
            }
            sp = fsoftplus(acc0 + acc1 + bfv);
        }
        // sum softplus over 30 samples + event-term dot, one reduction pass
#pragma unroll
        for (int off = 16; off; off >>= 1) {
            sp += __shfl_xor_sync(0xFFFFFFFFu, sp, off);
            q  += __shfl_xor_sync(0xFFFFFFFFu, q,  off);
        }
        const float lamb_int = (sp * (1.0f / NMC) + EPS_L) * dtl;
        float ev = 0.0f;
        if (l < len) ev = flog(fsoftplus(q + bfv) + EPS_L);
        out = ev - lamb_int;
    }
    if (lane == 0) g_part[wid] = out;
}

// --------------------------- Kernel 3: reduction -----------------------------
__global__ void __launch_bounds__(1024, 1)
reduce_kernel(float* __restrict__ out)
{
    __shared__ float sh[1024];
    const int t = threadIdx.x;
    float s = 0.0f;
    for (int i = t; i < TOTAL; i += 1024) s += g_part[i];
    sh[t] = s;
    __syncthreads();
#pragma unroll
    for (int ofs = 512; ofs; ofs >>= 1) {
        if (t < ofs) sh[t] += sh[t + ofs];
        __syncthreads();
    }
    if (t == 0) out[0] = -sh[0] * (1.0f / BATCH);
}

// ------------------------------- launcher ------------------------------------
extern "C" void kernel_launch(void* const* d_in, const int* in_sizes, int n_in,
                              void* d_out, int out_size)
{
    const float* seq  = nullptr;
    const float* Wrec = nullptr;
    const float* brec = nullptr;
    const float* Wf   = nullptr;
    const float* bf   = nullptr;
    const int*   lens = nullptr;
    for (int i = 0; i < n_in; i++) {
        const int s = in_sizes[i];
        if      (s == BATCH * MAXL)     seq  = (const float*)d_in[i];
        else if (s == 65 * SEVENH)      Wrec = (const float*)d_in[i];
        else if (s == SEVENH)           brec = (const float*)d_in[i];
        else if (s == 1)                bf   = (const float*)d_in[i];
        else if (s == HID) {
            if (!Wf) Wf = (const float*)d_in[i];
            else     lens = (const int*)d_in[i];
        }
    }

    scan_kernel<<<BATCH / 2, SEVENH>>>(seq, Wrec, brec, lens);
    mc_kernel<<<(TOTAL + 7) / 8, 256>>>(Wf, bf, lens);
    reduce_kernel<<<1, 1024>>>((float*)d_out);
}